// round 1
// baseline (speedup 1.0000x reference)
#include <cuda_runtime.h>
#include <cstdint>

// Problem constants
#define NUM   128
#define CIN   3
#define COUT  8
#define NX    31
#define NY    31
#define DIN   4
#define DOUT  6
#define POS   (NX*NY)      // 961
#define M256  256          // din^4
#define POq   48           // c_out*dout

// Shared memory layout (floats)
//  sx   : [3][4(point)][4(i)][128(n)] = 6144
//  sw   : [256(m)][48(p*6+o)]         = 12288
//  sab  : [16(ij)][128(n)]            = 2048
//  sbias: [48]
#define SX_OFF    0
#define SW_OFF    6144
#define SAB_OFF   (6144 + 12288)
#define SBIAS_OFF (6144 + 12288 + 2048)
#define SMEM_FLOATS (6144 + 12288 + 2048 + 48)
#define SMEM_BYTES  (SMEM_FLOATS * 4)

// ---- f32x2 packed helpers (sm_103a) ----
__device__ __forceinline__ unsigned long long dup_f32(float v) {
    unsigned long long r;
    asm("mov.b64 %0, {%1, %1};" : "=l"(r) : "r"(__float_as_uint(v)));
    return r;
}
__device__ __forceinline__ unsigned long long mul2(unsigned long long a, unsigned long long b) {
    unsigned long long r;
    asm("mul.rn.f32x2 %0, %1, %2;" : "=l"(r) : "l"(a), "l"(b));
    return r;
}
__device__ __forceinline__ unsigned long long fma2(unsigned long long a, unsigned long long b,
                                                   unsigned long long c) {
    unsigned long long r;
    asm("fma.rn.f32x2 %0, %1, %2, %3;" : "=l"(r) : "l"(a), "l"(b), "l"(c));
    return r;
}

extern __shared__ float smem[];

__global__ void __launch_bounds__(256, 2)
ttn_conv_kernel(const float* __restrict__ x,
                const float* __restrict__ w,
                const float* __restrict__ bias,
                float* __restrict__ out)
{
    const int pos = blockIdx.x;       // xx*31 + yy
    const int xx  = pos / NY;
    const int yy  = pos - xx * NY;
    const int tid = threadIdx.x;

    float* sx    = smem + SX_OFF;
    float* sw    = smem + SW_OFF;
    float* sab   = smem + SAB_OFF;
    float* sbias = smem + SBIAS_OFF;

    // ---- Stage x 2x2 patch: x[n,c,i, xx+dx, yy+dy], layout (32,32) spatial ----
    // sx[(c*4+pt)*4+i][n];  pt: 0=a(0,0) 1=b(1,0) 2=c(0,1) 3=d(1,1)
    #pragma unroll
    for (int s = tid; s < 6144; s += 256) {
        int n  = s & 127;
        int r  = s >> 7;           // 0..47
        int c  = r >> 4;
        int pt = (r >> 2) & 3;
        int i  = r & 3;
        int dx = pt & 1;
        int dy = pt >> 1;
        sx[r * 128 + n] = x[((n * CIN + c) * DIN + i) * 1024 + (xx + dx) * 32 + (yy + dy)];
    }
    // ---- Stage bias for this (xx,yy): sbias[p*6+o] ----
    if (tid < POq) {
        int p = tid / DOUT, o = tid - p * DOUT;
        sbias[tid] = bias[((p * NX + xx) * NY + yy) * DOUT + o];
    }

    const int n = tid & 127;     // which sample row
    const int g = tid >> 7;      // output half: outputs q in [g*24, g*24+24)

    unsigned long long acc[12];
    #pragma unroll
    for (int q = 0; q < 12; q++) acc[q] = 0ull;

    const unsigned swbase  = (unsigned)__cvta_generic_to_shared(sw) + (unsigned)(g * 96);
    const unsigned sababase = (unsigned)__cvta_generic_to_shared(sab);
    (void)sababase;

    #pragma unroll 1
    for (int c = 0; c < CIN; c++) {
        // ---- Stage weights for this c: 8 p-blocks of 1536 contiguous floats ----
        // global idx = ((c*8+p)*961 + pos)*1536 + m*6 + o ; smem: sw[m*48 + p*6 + o]
        #pragma unroll 1
        for (int v = tid; v < 3072; v += 256) {      // 3072 float4 loads total
            int p = v / 384;
            int r = v - p * 384;
            int e = r * 4;
            const float4 f = *(const float4*)(w + (size_t)((c * COUT + p) * POS + pos) * 1536 + e);
            const float* fp = &f.x;
            #pragma unroll
            for (int u = 0; u < 4; u++) {
                int ee = e + u;
                int m  = ee / 6;
                int o  = ee - m * 6;
                sw[m * POq + p * DOUT + o] = fp[u];
            }
        }
        __syncthreads();   // w (and on c==0: x, bias) staged

        // ---- Per-thread patch precursors for this c ----
        float av[4], bv[4], cv[4], dv[4];
        #pragma unroll
        for (int i = 0; i < 4; i++) {
            av[i] = sx[(c * 16 + 0  + i) * 128 + n];
            bv[i] = sx[(c * 16 + 4  + i) * 128 + n];
            cv[i] = sx[(c * 16 + 8  + i) * 128 + n];
            dv[i] = sx[(c * 16 + 12 + i) * 128 + n];
        }
        // ab -> smem (self-produced / self-consumed; allows dynamic ij loop)
        #pragma unroll
        for (int ij = 0; ij < 16; ij++)
            sab[ij * 128 + n] = av[ij >> 2] * bv[ij & 3];
        // cd duplicated into f32x2 lanes (registers, static indices only)
        unsigned long long cd2[16];
        #pragma unroll
        for (int kl = 0; kl < 16; kl++)
            cd2[kl] = dup_f32(cv[kl >> 2] * dv[kl & 3]);

        // ---- Main loop: m = ij*16 + kl ----
        #pragma unroll 1
        for (int ij = 0; ij < 16; ij++) {
            unsigned long long ab2 = dup_f32(sab[ij * 128 + n]);
            unsigned wa = swbase + (unsigned)(ij * 16 * 192);   // 192 B per m row
            #pragma unroll
            for (int kl = 0; kl < 16; kl++) {
                unsigned long long p2 = mul2(ab2, cd2[kl]);     // duplicated patch value
                unsigned maddr = wa + (unsigned)(kl * 192);
                #pragma unroll
                for (int j = 0; j < 6; j++) {
                    unsigned long long w0, w1;
                    asm("ld.shared.v2.b64 {%0, %1}, [%2];"
                        : "=l"(w0), "=l"(w1) : "r"(maddr + (unsigned)(j * 16)));
                    acc[2 * j]     = fma2(p2, w0, acc[2 * j]);
                    acc[2 * j + 1] = fma2(p2, w1, acc[2 * j + 1]);
                }
            }
        }
        __syncthreads();   // protect sw before next c overwrites it
    }

    // ---- Epilogue: unpack, add bias, store ----
    // acc[2j+s] holds outputs q = g*24 + 4j + 2s + {0,1};  out idx = (n*48+q)*961 + pos
    #pragma unroll
    for (int jj = 0; jj < 12; jj++) {
        float v0 = __uint_as_float((unsigned)(acc[jj] & 0xFFFFFFFFull));
        float v1 = __uint_as_float((unsigned)(acc[jj] >> 32));
        int q0 = g * 24 + (jj >> 1) * 4 + (jj & 1) * 2;
        out[(n * POq + q0)     * POS + pos] = v0 + sbias[q0];
        out[(n * POq + q0 + 1) * POS + pos] = v1 + sbias[q0 + 1];
    }
}

extern "C" void kernel_launch(void* const* d_in, const int* in_sizes, int n_in,
                              void* d_out, int out_size) {
    const float* x    = (const float*)d_in[0];
    const float* w    = (const float*)d_in[1];
    const float* bias = (const float*)d_in[2];
    float* out        = (float*)d_out;
    (void)in_sizes; (void)n_in; (void)out_size;

    cudaFuncSetAttribute(ttn_conv_kernel,
                         cudaFuncAttributeMaxDynamicSharedMemorySize, SMEM_BYTES);
    ttn_conv_kernel<<<POS, 256, SMEM_BYTES>>>(x, w, bias, out);
}

// round 2
// speedup vs baseline: 1.3574x; 1.3574x over previous
#include <cuda_runtime.h>
#include <cstdint>

// Problem constants
#define NUM   128
#define CIN   3
#define COUT  8
#define NX    31
#define NY    31
#define DIN   4
#define DOUT  6
#define POS   (NX*NY)      // 961
#define POq   48           // c_out*dout

// sw row stride (floats): padded from 48 -> 56 (224B, 16B aligned, kills STS conflicts)
#define SWSTR 56

// Shared memory layout (floats)
//  sxc  : [16(pt*4+i)][128(n)]   = 2048   (per-c x slice)
//  sw   : [256(m)][SWSTR]        = 14336
//  sbias: [48]
#define SXC_OFF   0
#define SW_OFF    2048
#define SBIAS_OFF (2048 + 256*SWSTR)
#define SMEM_FLOATS (2048 + 256*SWSTR + 48)
#define SMEM_BYTES  (SMEM_FLOATS * 4)

// ---- f32x2 packed helpers (sm_103a) ----
__device__ __forceinline__ unsigned long long dup_f32(float v) {
    unsigned long long r;
    asm("mov.b64 %0, {%1, %1};" : "=l"(r) : "r"(__float_as_uint(v)));
    return r;
}
__device__ __forceinline__ unsigned long long mul2(unsigned long long a, unsigned long long b) {
    unsigned long long r;
    asm("mul.rn.f32x2 %0, %1, %2;" : "=l"(r) : "l"(a), "l"(b));
    return r;
}
__device__ __forceinline__ unsigned long long fma2(unsigned long long a, unsigned long long b,
                                                   unsigned long long c) {
    unsigned long long r;
    asm("fma.rn.f32x2 %0, %1, %2, %3;" : "=l"(r) : "l"(a), "l"(b), "l"(c));
    return r;
}

extern __shared__ float smem[];

__global__ void __launch_bounds__(128, 3)
ttn_conv_kernel(const float* __restrict__ x,
                const float* __restrict__ w,
                const float* __restrict__ bias,
                float* __restrict__ out)
{
    const int pos = blockIdx.x;       // xx*31 + yy
    const int xx  = pos / NY;
    const int yy  = pos - xx * NY;
    const int tid = threadIdx.x;

    float* sxc   = smem + SXC_OFF;
    float* sw    = smem + SW_OFF;
    float* sbias = smem + SBIAS_OFF;

    const int nh = tid & 63;          // sample pair id
    const int g  = tid >> 6;          // output half: q in [g*24, g*24+24)
    const int n0 = nh;
    const int n1 = nh + 64;

    // bias staged once
    if (tid < POq) {
        int p = tid / DOUT, o = tid - p * DOUT;
        sbias[tid] = bias[((p * NX + xx) * NY + yy) * DOUT + o];
    }

    unsigned long long acc0[12], acc1[12];
    #pragma unroll
    for (int q = 0; q < 12; q++) { acc0[q] = 0ull; acc1[q] = 0ull; }

    const unsigned swbase = (unsigned)__cvta_generic_to_shared(sw) + (unsigned)(g * 96);

    #pragma unroll 1
    for (int c = 0; c < CIN; c++) {
        if (c) __syncthreads();   // previous compute done before restaging

        // ---- Stage x slice for this c: sxc[(pt*4+i)*128 + n] ----
        // pt: 0=a(0,0) 1=b(+x,0) 2=c(0,+y) 3=d(+x,+y)
        #pragma unroll
        for (int s = tid; s < 2048; s += 128) {
            int n  = s & 127;
            int r  = s >> 7;           // 0..15
            int pt = r >> 2;
            int i  = r & 3;
            int dx = pt & 1;
            int dy = pt >> 1;
            sxc[r * 128 + n] = x[((n * CIN + c) * DIN + i) * 1024 + (xx + dx) * 32 + (yy + dy)];
        }

        // ---- Stage weights for this c: sw[m*SWSTR + p*6 + o] ----
        // global: w[((c*8+p)*961 + pos)*1536 + m*6 + o]
        #pragma unroll
        for (int v = tid; v < 3072; v += 128) {      // float4 granules
            int p = v / 384;
            int r = v - p * 384;
            int e = r * 4;
            const float4 f = *(const float4*)(w + (size_t)((c * COUT + p) * POS + pos) * 1536 + e);
            const float* fp = &f.x;
            #pragma unroll
            for (int u = 0; u < 4; u++) {
                int ee = e + u;
                int m  = ee / 6;
                int o  = ee - m * 6;
                sw[m * SWSTR + p * DOUT + o] = fp[u];
            }
        }
        __syncthreads();   // sxc + sw staged

        // ---- Per-thread patch precursors (2 samples) ----
        float av0[4], bv0[4], cv0[4], dv0[4];
        float av1[4], bv1[4], cv1[4], dv1[4];
        #pragma unroll
        for (int i = 0; i < 4; i++) {
            av0[i] = sxc[(0  + i) * 128 + n0];  av1[i] = sxc[(0  + i) * 128 + n1];
            bv0[i] = sxc[(4  + i) * 128 + n0];  bv1[i] = sxc[(4  + i) * 128 + n1];
            cv0[i] = sxc[(8  + i) * 128 + n0];  cv1[i] = sxc[(8  + i) * 128 + n1];
            dv0[i] = sxc[(12 + i) * 128 + n0];  dv1[i] = sxc[(12 + i) * 128 + n1];
        }
        // cd pre-duplicated into f32x2 lanes (registers, static indices)
        unsigned long long cd0[16], cd1[16];
        #pragma unroll
        for (int kl = 0; kl < 16; kl++) {
            cd0[kl] = dup_f32(cv0[kl >> 2] * dv0[kl & 3]);
            cd1[kl] = dup_f32(cv1[kl >> 2] * dv1[kl & 3]);
        }

        // ---- Main loop: m = ij*16 + kl ----
        #pragma unroll 1
        for (int ij = 0; ij < 16; ij++) {
            unsigned long long ab0 = dup_f32(av0[ij >> 2] * bv0[ij & 3]);
            unsigned long long ab1 = dup_f32(av1[ij >> 2] * bv1[ij & 3]);
            unsigned wa = swbase + (unsigned)(ij * 16 * (SWSTR * 4));
            #pragma unroll
            for (int kl = 0; kl < 16; kl++) {
                unsigned long long p0 = mul2(ab0, cd0[kl]);   // patch value, duplicated lanes
                unsigned long long p1 = mul2(ab1, cd1[kl]);
                unsigned maddr = wa + (unsigned)(kl * (SWSTR * 4));
                #pragma unroll
                for (int j = 0; j < 6; j++) {
                    unsigned long long w0, w1;
                    asm("ld.shared.v2.b64 {%0, %1}, [%2];"
                        : "=l"(w0), "=l"(w1) : "r"(maddr + (unsigned)(j * 16)));
                    acc0[2 * j]     = fma2(p0, w0, acc0[2 * j]);
                    acc0[2 * j + 1] = fma2(p0, w1, acc0[2 * j + 1]);
                    acc1[2 * j]     = fma2(p1, w0, acc1[2 * j]);
                    acc1[2 * j + 1] = fma2(p1, w1, acc1[2 * j + 1]);
                }
            }
        }
    }

    // ---- Epilogue: unpack, add bias, store ----
    // acc*[2j+s] holds outputs q = g*24 + 4j + 2s + {0,1};  out idx = (n*48+q)*961 + pos
    #pragma unroll
    for (int jj = 0; jj < 12; jj++) {
        int q0 = g * 24 + (jj >> 1) * 4 + (jj & 1) * 2;
        float u0 = __uint_as_float((unsigned)(acc0[jj] & 0xFFFFFFFFull));
        float u1 = __uint_as_float((unsigned)(acc0[jj] >> 32));
        out[(n0 * POq + q0)     * POS + pos] = u0 + sbias[q0];
        out[(n0 * POq + q0 + 1) * POS + pos] = u1 + sbias[q0 + 1];
        float v0 = __uint_as_float((unsigned)(acc1[jj] & 0xFFFFFFFFull));
        float v1 = __uint_as_float((unsigned)(acc1[jj] >> 32));
        out[(n1 * POq + q0)     * POS + pos] = v0 + sbias[q0];
        out[(n1 * POq + q0 + 1) * POS + pos] = v1 + sbias[q0 + 1];
    }
}

extern "C" void kernel_launch(void* const* d_in, const int* in_sizes, int n_in,
                              void* d_out, int out_size) {
    const float* x    = (const float*)d_in[0];
    const float* w    = (const float*)d_in[1];
    const float* bias = (const float*)d_in[2];
    float* out        = (float*)d_out;
    (void)in_sizes; (void)n_in; (void)out_size;

    cudaFuncSetAttribute(ttn_conv_kernel,
                         cudaFuncAttributeMaxDynamicSharedMemorySize, SMEM_BYTES);
    ttn_conv_kernel<<<POS, 128, SMEM_BYTES>>>(x, w, bias, out);
}

// round 6
// speedup vs baseline: 2.0269x; 1.4932x over previous
#include <cuda_runtime.h>
#include <cuda_fp16.h>
#include <cstdint>

#define CIN 3
#define NY  31
#define POS 961
#define POq 48

// ---- smem layout (bytes) ----
#define SBIAS 0          // 48 floats
#define AHI0  1024       // A tiles: 128 rows x 64B (32 halves), swizzled
#define ALO0  9216
#define BHI0  17408      // B tiles: 32 rows x 128B (48 halves used), swizzled
#define BLO0  21504
#define AHI1  25600
#define ALO1  33792
#define BHI1  41984
#define BLO1  46080
#define SMEM_BYTES 50176

// A-tile swizzle: row is 64B = 4 chunks of 16B. 2-bit XOR only (kc in 0..3).
// Conflict-free for both LDSM reads (8 consecutive rows, fixed kc) and
// STS writes (32 consecutive rows, fixed kc).
#define ASWZ(row, kc) ((uint32_t)(((kc) ^ (((row) >> 1) & 3u) ^ (((row) >> 3) & 3u))))

__device__ __forceinline__ uint32_t smem_u32(const void* p) {
    uint32_t a;
    asm("{ .reg .u64 t; cvta.to.shared.u64 t, %1; cvt.u32.u64 %0, t; }" : "=r"(a) : "l"(p));
    return a;
}
__device__ __forceinline__ void ldsm_x4(uint32_t& r0, uint32_t& r1, uint32_t& r2, uint32_t& r3,
                                        uint32_t a) {
    asm volatile("ldmatrix.sync.aligned.m8n8.x4.shared.b16 {%0,%1,%2,%3}, [%4];"
                 : "=r"(r0), "=r"(r1), "=r"(r2), "=r"(r3) : "r"(a));
}
__device__ __forceinline__ void ldsm_x2t(uint32_t& r0, uint32_t& r1, uint32_t a) {
    asm volatile("ldmatrix.sync.aligned.m8n8.x2.trans.shared.b16 {%0,%1}, [%2];"
                 : "=r"(r0), "=r"(r1) : "r"(a));
}
__device__ __forceinline__ void mma16816(float& d0, float& d1, float& d2, float& d3,
                                         uint32_t a0, uint32_t a1, uint32_t a2, uint32_t a3,
                                         uint32_t b0, uint32_t b1) {
    asm volatile("mma.sync.aligned.m16n8k16.row.col.f32.f16.f16.f32 "
                 "{%0,%1,%2,%3}, {%4,%5,%6,%7}, {%8,%9}, {%0,%1,%2,%3};"
                 : "+f"(d0), "+f"(d1), "+f"(d2), "+f"(d3)
                 : "r"(a0), "r"(a1), "r"(a2), "r"(a3), "r"(b0), "r"(b1));
}
// split v -> fp16 hi + fp16 lo (residual); pack pairs into b32
__device__ __forceinline__ void split2(float v0, float v1, uint32_t& hi, uint32_t& lo) {
    __half h0 = __float2half_rn(v0), h1 = __float2half_rn(v1);
    __half l0 = __float2half_rn(v0 - __half2float(h0));
    __half l1 = __float2half_rn(v1 - __half2float(h1));
    hi = (uint32_t)__half_as_ushort(h0) | ((uint32_t)__half_as_ushort(h1) << 16);
    lo = (uint32_t)__half_as_ushort(l0) | ((uint32_t)__half_as_ushort(l1) << 16);
}
__device__ __forceinline__ void sts64(uint32_t a, uint32_t v0, uint32_t v1) {
    asm volatile("st.shared.v2.b32 [%0], {%1,%2};" :: "r"(a), "r"(v0), "r"(v1) : "memory");
}
__device__ __forceinline__ void sts16(uint32_t a, unsigned short v) {
    asm volatile("st.shared.u16 [%0], %1;" :: "r"(a), "h"(v) : "memory");
}

extern __shared__ char smem[];

__global__ void __launch_bounds__(128, 2)
ttn_conv_hmma_kernel(const float* __restrict__ x,
                     const float* __restrict__ w,
                     const float* __restrict__ bias,
                     float* __restrict__ out)
{
    const int pos  = blockIdx.x;
    const int xx   = pos / NY;
    const int yy   = pos - xx * NY;
    const int tid  = threadIdx.x;
    const int lane = tid & 31;
    const int wid  = tid >> 5;
    const uint32_t sb = smem_u32(smem);
    float* sbias = (float*)(smem + SBIAS);

    if (tid < POq) {
        int p = tid / 6, o = tid - p * 6;
        sbias[tid] = bias[((p * 31 + xx) * 31 + yy) * 6 + o];
    }

    const int bp  = tid >> 4;     // p block (0..7) for weight loads
    const int t16 = tid & 15;

    float D[48];
    #pragma unroll
    for (int i = 0; i < 48; i++) D[i] = 0.f;

    float ab[16], cd[16];
    float4 f4[3];

    // ---- helpers as lambdas ----
    auto load_abcd = [&](int c) {
        const float* xp = x + ((size_t)tid * CIN + c) * 4096 + xx * 32 + yy;
        float av[4], bv[4], cv[4], dv[4];
        #pragma unroll
        for (int i = 0; i < 4; i++) {
            av[i] = xp[i * 1024];
            bv[i] = xp[i * 1024 + 32];
            cv[i] = xp[i * 1024 + 1];
            dv[i] = xp[i * 1024 + 33];
        }
        #pragma unroll
        for (int t = 0; t < 16; t++) {
            ab[t] = av[t >> 2] * bv[t & 3];
            cd[t] = cv[t >> 2] * dv[t & 3];
        }
    };
    auto ldg_w = [&](int chunk) {
        int c = chunk >> 3, s = chunk & 7;
        const float* gw = w + ((size_t)(c * 8 + bp) * POS + pos) * 1536 + s * 192;
        #pragma unroll
        for (int r = 0; r < 3; r++) f4[r] = ((const float4*)gw)[t16 + 16 * r];
    };
    auto stage = [&](int chunk) {
        const int s   = chunk & 7;
        const int buf = chunk & 1;
        const uint32_t ah = sb + (buf ? AHI1 : AHI0);
        const uint32_t al = sb + (buf ? ALO1 : ALO0);
        const uint32_t bh = sb + (buf ? BHI1 : BHI0);
        const uint32_t bl = sb + (buf ? BLO1 : BLO0);

        // A: this thread's row (m = tid), k-local 0..31 -> values ab[2s+h]*cd[j]
        #pragma unroll
        for (int h = 0; h < 2; h++) {
            const float abv = ab[s * 2 + h];
            #pragma unroll
            for (int g4 = 0; g4 < 4; g4++) {
                float v0 = abv * cd[g4 * 4 + 0];
                float v1 = abv * cd[g4 * 4 + 1];
                float v2 = abv * cd[g4 * 4 + 2];
                float v3 = abv * cd[g4 * 4 + 3];
                uint32_t h01, l01, h23, l23;
                split2(v0, v1, h01, l01);
                split2(v2, v3, h23, l23);
                uint32_t kc  = (uint32_t)(h * 2 + (g4 >> 1));
                uint32_t off = (uint32_t)tid * 64u + 16u * ASWZ((uint32_t)tid, kc)
                             + (uint32_t)(g4 & 1) * 8u;
                sts64(ah + off, h01, h23);
                sts64(al + off, l01, l23);
            }
        }
        // B: transpose [k-local][o] -> rows k (128B, swizzled), col n = bp*6+o
        #pragma unroll
        for (int r = 0; r < 3; r++) {
            const float* fp = &f4[r].x;
            #pragma unroll
            for (int u = 0; u < 4; u++) {
                int e = t16 * 4 + u + r * 64;       // 0..191
                int k = e / 6, o = e - 6 * k;
                uint32_t n   = (uint32_t)(bp * 6 + o);
                uint32_t off = (uint32_t)k * 128u + 16u * ((n >> 3) ^ ((uint32_t)k & 7u))
                             + (n & 7u) * 2u;
                float v = fp[u];
                __half hh = __float2half_rn(v);
                __half hl = __float2half_rn(v - __half2float(hh));
                sts16(bh + off, __half_as_ushort(hh));
                sts16(bl + off, __half_as_ushort(hl));
            }
        }
    };
    auto compute = [&](int buf) {
        const uint32_t ah = sb + (buf ? AHI1 : AHI0);
        const uint32_t al = sb + (buf ? ALO1 : ALO0);
        const uint32_t bh = sb + (buf ? BHI1 : BHI0);
        const uint32_t bl = sb + (buf ? BLO1 : BLO0);
        #pragma unroll
        for (int s16 = 0; s16 < 2; s16++) {
            // B fragments for this k16: 6 n-tiles, hi+lo
            uint32_t Bh[12], Bl[12];
            uint32_t krow = (uint32_t)(s16 * 16 + (lane & 15));
            #pragma unroll
            for (int nt = 0; nt < 6; nt++) {
                uint32_t boff = krow * 128u + 16u * ((uint32_t)nt ^ (krow & 7u));
                ldsm_x2t(Bh[nt * 2], Bh[nt * 2 + 1], bh + boff);
                ldsm_x2t(Bl[nt * 2], Bl[nt * 2 + 1], bl + boff);
            }
            #pragma unroll
            for (int mt = 0; mt < 2; mt++) {
                uint32_t row = (uint32_t)(wid * 32 + mt * 16 + (lane & 15));
                uint32_t kc  = (uint32_t)(s16 * 2 + (lane >> 4));
                uint32_t aoff = row * 64u + 16u * ASWZ(row, kc);
                uint32_t Ah[4], Al[4];
                ldsm_x4(Ah[0], Ah[1], Ah[2], Ah[3], ah + aoff);
                ldsm_x4(Al[0], Al[1], Al[2], Al[3], al + aoff);
                #pragma unroll
                for (int nt = 0; nt < 6; nt++) {
                    float* d = D + (mt * 6 + nt) * 4;
                    mma16816(d[0], d[1], d[2], d[3],
                             Ah[0], Ah[1], Ah[2], Ah[3], Bh[nt * 2], Bh[nt * 2 + 1]);
                    mma16816(d[0], d[1], d[2], d[3],
                             Ah[0], Ah[1], Ah[2], Ah[3], Bl[nt * 2], Bl[nt * 2 + 1]);
                    mma16816(d[0], d[1], d[2], d[3],
                             Al[0], Al[1], Al[2], Al[3], Bh[nt * 2], Bh[nt * 2 + 1]);
                }
            }
        }
    };

    // ---- pipeline ----
    load_abcd(0);
    ldg_w(0);
    stage(0);
    __syncthreads();

    #pragma unroll 1
    for (int chunk = 0; chunk < 24; chunk++) {
        if (chunk < 23) ldg_w(chunk + 1);
        if (chunk < 23 && ((chunk + 1) & 7) == 0) load_abcd((chunk + 1) >> 3);
        compute(chunk & 1);
        if (chunk < 23) stage(chunk + 1);
        __syncthreads();
    }

    // ---- epilogue ----
    #pragma unroll
    for (int mt = 0; mt < 2; mt++)
        #pragma unroll
        for (int nt = 0; nt < 6; nt++)
            #pragma unroll
            for (int r = 0; r < 4; r++) {
                int row = wid * 32 + mt * 16 + (lane >> 2) + ((r >= 2) ? 8 : 0);
                int q   = nt * 8 + (lane & 3) * 2 + (r & 1);
                out[((size_t)row * POq + q) * POS + pos] = D[(mt * 6 + nt) * 4 + r] + sbias[q];
            }
}

extern "C" void kernel_launch(void* const* d_in, const int* in_sizes, int n_in,
                              void* d_out, int out_size) {
    const float* x    = (const float*)d_in[0];
    const float* w    = (const float*)d_in[1];
    const float* bias = (const float*)d_in[2];
    float* out        = (float*)d_out;
    (void)in_sizes; (void)n_in; (void)out_size;

    cudaFuncSetAttribute(ttn_conv_hmma_kernel,
                         cudaFuncAttributeMaxDynamicSharedMemorySize, SMEM_BYTES);
    ttn_conv_hmma_kernel<<<POS, 128, SMEM_BYTES>>>(x, w, bias, out);
}